// round 16
// baseline (speedup 1.0000x reference)
#include <cuda_runtime.h>
#include <cuda_fp16.h>
#include <cstdint>

// ---------------------------------------------------------------------------
// HVGGBlock in tangent space; convs via mma.sync m16n8k16 fp16 implicit GEMM.
// A tile in smem as [s2-half][pixel][16ch], 48B slots (conflict-free
// ldmatrix.x4). Weight pack permutes couts so each epilogue lane owns a
// contiguous 16B channel chunk -> STG.128 (canonical channel-last preserved).
// BN statistics fused into both conv epilogues (no standalone stats passes).
// CTA = 32x8 outputs, warp = 1 pixel row, __launch_bounds__(256,4).
//   logmap0(project(expmap0(u))) == clampnorm(u, R), R = artanh(1-1e-4)
// ---------------------------------------------------------------------------

#define NB   8
#define CH   32
#define HH   256
#define WW   256
#define PLANE (HH*WW)
#define IMG   (CH*PLANE)
#define NPIX  (NB*PLANE)

#define R_CLAMP 4.9517188f
#define MAXN    0.9999f

__device__ __align__(16) __half g_bufB[NB*IMG];   // channel-last: [pix][32]
__device__ __align__(16) __half g_bufA[NB*IMG];   // channel-last
__device__ float g_stats[128];   // [0:32) sum1 [32:64) sq1 [64:96) sum2 [96:128) sq2
__device__ __align__(16) uint32_t g_wpack[2*18*4*32*2];  // fp16 B-frags

__global__ void noop_kernel() {}   // profiler launch-alignment

__device__ __forceinline__ uint32_t smem_u32_of(const void* p) {
    uint32_t a;
    asm("{ .reg .u64 t; cvta.to.shared.u64 t, %1; cvt.u32.u64 %0, t; }" : "=r"(a) : "l"(p));
    return a;
}

#define LDSM_X4(r0, r1, r2, r3, addr) \
    asm volatile("ldmatrix.sync.aligned.m8n8.x4.shared.b16 {%0,%1,%2,%3}, [%4];" \
        : "=r"(r0), "=r"(r1), "=r"(r2), "=r"(r3) : "r"(addr))

// ---- weight pack (+ zero g_stats): [layer][step][Nt][lane] -> {b0,b1} -------
// cout permutation: column gd of N-tile Nt -> cout = 8*(gd>>1) + 2*Nt + (gd&1)
__global__ void __launch_bounds__(256) pack_w_kernel(const float* __restrict__ w1,
                                                     const float* __restrict__ w2) {
    if (blockIdx.x == 0 && threadIdx.x < 128) g_stats[threadIdx.x] = 0.f;
    int id = blockIdx.x * 256 + threadIdx.x;
    if (id >= 4608) return;
    int lay = id / 2304;
    int r   = id - lay * 2304;
    int l   = r & 31;
    int Nt  = (r >> 5) & 3;
    int st  = r >> 7;                 // 0..17
    int t   = st >> 1, s2 = st & 1;
    int tig = l & 3, gd = l >> 2;
    int co  = 8 * (gd >> 1) + 2 * Nt + (gd & 1);   // permuted cout
    int ch0 = s2 * 16 + 2 * tig;
    const float* w = lay ? w2 : w1;
    __half2 h0 = __floats2half2_rn(w[(co * CH + ch0    ) * 9 + t],
                                   w[(co * CH + ch0 + 1) * 9 + t]);
    __half2 h1 = __floats2half2_rn(w[(co * CH + ch0 + 8) * 9 + t],
                                   w[(co * CH + ch0 + 9) * 9 + t]);
    uint2* dst = (uint2*)(g_wpack + lay * 4608);
    dst[(st * 4 + Nt) * 32 + l] = make_uint2(*(const uint32_t*)&h0,
                                             *(const uint32_t*)&h1);
}

// ---- fused conv kernel -------------------------------------------------------
#define SLOT    48
#define S2OFF   (340*SLOT)            // 16320
#define SMEM_BYTES (2*S2OFF)          // 32640 dynamic

// MODE 0: src = x (fp32 NCHW), logmap, dst = g_bufB, stats -> g_stats[0:64)
// MODE 1: src = g_bufB, BN(stats[0:64))+clamp+relu, dst = g_bufA, stats -> [64:128)
template<int MODE>
__global__ void __launch_bounds__(256, 4)
conv_fused_kernel(const float* __restrict__ ext, const float* __restrict__ bias,
                  const float* __restrict__ gamma, const float* __restrict__ beta) {
    extern __shared__ __align__(16) char smem[];
    __shared__ float s_aff[64];
    __shared__ float s_st[64];

    const int tid  = threadIdx.x;
    const int wid  = tid >> 5;
    const int lane = tid & 31;
    const int gid  = lane >> 2;
    const int tig  = lane & 3;
    const int n    = blockIdx.z;
    const int gy0  = blockIdx.y * 8;
    const int gx0  = blockIdx.x * 32;

    if (tid < 64) s_st[tid] = 0.f;
    if (MODE == 1) {
        if (tid < 32) {
            const float inv = 1.0f / (float)NPIX;
            float m   = g_stats[tid] * inv;
            float var = fmaxf(g_stats[32 + tid] * inv - m * m, 0.f);
            float is  = rsqrtf(var + 1e-5f);
            float sc  = gamma[tid] * is;
            s_aff[tid]      = sc;
            s_aff[32 + tid] = beta[tid] - m * sc;
        }
        __syncthreads();
    }

    // ---- build: quad-cooperative; lane's 8 channels are one 16B STS.128 ------
    const int lq = tid & 3;          // channels 8*lq .. 8*lq+7
    const int c0 = lq * 8;
    char* wr = smem + (lq >> 1) * S2OFF + (lq & 1) * 16;
    for (int p0 = tid >> 2; p0 < 384; p0 += 64) {
        bool act = (p0 < 340);
        int r = p0 / 34, c = p0 - r * 34;
        int gy = gy0 + r - 1, gx = gx0 + c - 1;
        bool inb = act && ((unsigned)gy < 256u) && ((unsigned)gx < 256u);
        float v[8]; float ss = 0.f;
        if (inb) {
            if (MODE == 0) {
                const float* sp = ext + n * IMG + c0 * PLANE + gy * WW + gx;
#pragma unroll
                for (int j = 0; j < 8; j++) { v[j] = sp[j * PLANE]; ss += v[j] * v[j]; }
            } else {
                uint4 hv = ((const uint4*)g_bufB)[(n * PLANE + gy * WW + gx) * 4 + lq];
                const uint32_t hw_[4] = {hv.x, hv.y, hv.z, hv.w};
#pragma unroll
                for (int j2 = 0; j2 < 4; j2++) {
                    float2 f = __half22float2(*(const __half2*)&hw_[j2]);
                    float u0 = f.x * s_aff[c0 + 2*j2]     + s_aff[32 + c0 + 2*j2];
                    float u1 = f.y * s_aff[c0 + 2*j2 + 1] + s_aff[32 + c0 + 2*j2 + 1];
                    v[2*j2] = u0; v[2*j2+1] = u1;
                    ss += u0 * u0 + u1 * u1;
                }
            }
        } else {
#pragma unroll
            for (int j = 0; j < 8; j++) v[j] = 0.f;
        }
        ss += __shfl_xor_sync(0xffffffffu, ss, 1);
        ss += __shfl_xor_sync(0xffffffffu, ss, 2);
        float f;
        if (MODE == 0) {
            float nrm = sqrtf(ss);
            float nn  = fmaxf(nrm, 1e-5f);
            float t   = fminf(nn, 1.f - 1e-5f);
            f = 0.5f * (log1pf(t) - log1pf(-t)) / nn;              // logmap0
        } else {
            float nrm = sqrtf(ss);
            f = (nrm > R_CLAMP) ? (R_CLAMP / nrm) : 1.0f;          // clampnorm
        }
        if (act) {
            uint32_t hh[4];
#pragma unroll
            for (int j = 0; j < 4; j++) {
                float u0 = v[2*j] * f, u1 = v[2*j+1] * f;
                if (MODE == 1) { u0 = fmaxf(u0, 0.f); u1 = fmaxf(u1, 0.f); }
                __half2 h = __floats2half2_rn(u0, u1);
                hh[j] = *(const uint32_t*)&h;
            }
            *(uint4*)(wr + p0 * SLOT) = make_uint4(hh[0], hh[1], hh[2], hh[3]);
        }
    }
    __syncthreads();

    // ---- implicit GEMM: warp owns 1 pixel row, 2 M-tiles, N=32, K=288 --------
    const uint2* wp = ((const uint2*)(g_wpack + MODE * 4608)) + lane;
    float acc[2][4][4];
#pragma unroll
    for (int i = 0; i < 2; i++)
#pragma unroll
        for (int Nt = 0; Nt < 4; Nt++)
#pragma unroll
            for (int j = 0; j < 4; j++) acc[i][Nt][j] = 0.f;

    const uint32_t abase = smem_u32_of(smem)
                         + (uint32_t)((lane & 15) * SLOT + (lane >> 4) * 16)
                         + (uint32_t)(wid * 34 * SLOT);

#pragma unroll
    for (int st = 0; st < 18; st++) {
        const int t  = st >> 1;
        const int s2 = st & 1;
        const int ky = (t >= 6) ? 2 : (t >= 3 ? 1 : 0);
        const int kx = t - ky * 3;

        uint2 b0 = wp[0], b1 = wp[32], b2 = wp[64], b3 = wp[96];
        wp += 128;

        const uint32_t rowaddr = abase + (uint32_t)(s2 * S2OFF + (ky * 34 + kx) * SLOT);
#pragma unroll
        for (int i = 0; i < 2; i++) {
            uint32_t a0, a1, a2, a3;
            LDSM_X4(a0, a1, a2, a3, rowaddr + (uint32_t)(i * 16 * SLOT));
#define MMA_NT(BB, NT)                                                          \
            asm volatile(                                                       \
                "mma.sync.aligned.m16n8k16.row.col.f32.f16.f16.f32 "            \
                "{%0,%1,%2,%3}, {%4,%5,%6,%7}, {%8,%9}, {%0,%1,%2,%3};"         \
                : "+f"(acc[i][NT][0]), "+f"(acc[i][NT][1]),                     \
                  "+f"(acc[i][NT][2]), "+f"(acc[i][NT][3])                      \
                : "r"(a0), "r"(a1), "r"(a2), "r"(a3),                           \
                  "r"(BB.x), "r"(BB.y))
            MMA_NT(b0, 0); MMA_NT(b1, 1); MMA_NT(b2, 2); MMA_NT(b3, 3);
#undef MMA_NT
        }
    }

    // ---- epilogue: bias + clampnorm + STG.128 + fused BN stats ---------------
    // lane tig owns channels 8*tig..8*tig+7; pixels processed sequentially.
    const float4* bp = (const float4*)(bias + 8 * tig);
    const float4 bsa = bp[0], bsb = bp[1];
    const float bch[8] = {bsa.x, bsa.y, bsa.z, bsa.w, bsb.x, bsb.y, bsb.z, bsb.w};

    float sAcc[8], qAcc[8];
#pragma unroll
    for (int j = 0; j < 8; j++) { sAcc[j] = 0.f; qAcc[j] = 0.f; }

    uint4* o4 = (uint4*)(MODE == 0 ? g_bufB : g_bufA) + (size_t)n * PLANE * 4;
    const int pixrow = (gy0 + wid) * WW + gx0;
#pragma unroll
    for (int i = 0; i < 2; i++) {
#pragma unroll
        for (int hf = 0; hf < 2; hf++) {      // hf=0: cols 0,1 ; hf=1: cols 2,3
            float v[8]; float ss = 0.f;
#pragma unroll
            for (int Nt = 0; Nt < 4; Nt++) {
                float u0 = acc[i][Nt][2*hf]     + bch[2 * Nt];
                float u1 = acc[i][Nt][2*hf + 1] + bch[2 * Nt + 1];
                v[2 * Nt] = u0; v[2 * Nt + 1] = u1;
                ss += u0 * u0 + u1 * u1;
            }
            ss += __shfl_xor_sync(0xffffffffu, ss, 1);
            ss += __shfl_xor_sync(0xffffffffu, ss, 2);
            float nrm = sqrtf(ss);
            float f = (nrm > R_CLAMP) ? (R_CLAMP / nrm) : 1.0f;
            uint32_t h[4];
#pragma unroll
            for (int Nt = 0; Nt < 4; Nt++) {
                float u0 = v[2 * Nt] * f, u1 = v[2 * Nt + 1] * f;
                __half2 hh = __floats2half2_rn(u0, u1);
                h[Nt] = *(const uint32_t*)&hh;
                sAcc[2 * Nt]     += u0;  qAcc[2 * Nt]     += u0 * u0;
                sAcc[2 * Nt + 1] += u1;  qAcc[2 * Nt + 1] += u1 * u1;
            }
            int pix = pixrow + i * 16 + gid + hf * 8;
            o4[pix * 4 + tig] = make_uint4(h[0], h[1], h[2], h[3]);
        }
    }

    // reduce over the 8 lanes sharing this channel set (same tig, gid 0..7)
#pragma unroll
    for (int j = 0; j < 8; j++) {
#pragma unroll
        for (int o = 4; o <= 16; o <<= 1) {
            sAcc[j] += __shfl_xor_sync(0xffffffffu, sAcc[j], o);
            qAcc[j] += __shfl_xor_sync(0xffffffffu, qAcc[j], o);
        }
    }
    if (gid == 0) {
#pragma unroll
        for (int j = 0; j < 8; j++) {
            atomicAdd(&s_st[8 * tig + j],      sAcc[j]);
            atomicAdd(&s_st[32 + 8 * tig + j], qAcc[j]);
        }
    }
    __syncthreads();
    if (tid < 64) atomicAdd(&g_stats[MODE * 64 + tid], s_st[tid]);
}

// ---- bn2 + clamp + relu + expmap0 + project : bufA (ch-last) -> out (NCHW) ---
__global__ void __launch_bounds__(256) final_kernel(const float* __restrict__ gamma,
                                                    const float* __restrict__ beta,
                                                    float* __restrict__ out) {
    __shared__ float s_aff[64];
    if (threadIdx.x < 32) {
        int c = threadIdx.x;
        const float inv = 1.0f / (float)NPIX;
        float m   = g_stats[64 + c] * inv;
        float var = fmaxf(g_stats[96 + c] * inv - m * m, 0.f);
        float is  = rsqrtf(var + 1e-5f);
        float sc  = gamma[c] * is;
        s_aff[c]      = sc;
        s_aff[32 + c] = beta[c] - m * sc;
    }
    __syncthreads();

    int q  = blockIdx.x * 64 + (threadIdx.x >> 2);
    int lq = threadIdx.x & 3;
    int c0 = lq * 8;
    int n  = q >> 16, hw = q & 65535;

    uint4 hv = ((const uint4*)g_bufA)[(size_t)q * 4 + lq];
    const uint32_t hw_[4] = {hv.x, hv.y, hv.z, hv.w};
    float u[8]; float ss = 0.f;
#pragma unroll
    for (int j2 = 0; j2 < 4; j2++) {
        float2 f = __half22float2(*(const __half2*)&hw_[j2]);
        float u0 = f.x * s_aff[c0 + 2*j2]     + s_aff[32 + c0 + 2*j2];
        float u1 = f.y * s_aff[c0 + 2*j2 + 1] + s_aff[32 + c0 + 2*j2 + 1];
        u[2*j2] = u0; u[2*j2+1] = u1;
        ss += u0 * u0 + u1 * u1;
    }
    ss += __shfl_xor_sync(0xffffffffu, ss, 1);
    ss += __shfl_xor_sync(0xffffffffu, ss, 2);
    float nrm = sqrtf(ss);
    float f1 = (nrm > R_CLAMP) ? (R_CLAMP / nrm) : 1.0f;
    float ss2 = 0.f;
#pragma unroll
    for (int j = 0; j < 8; j++) { u[j] = fmaxf(u[j] * f1, 0.f); ss2 += u[j] * u[j]; }
    ss2 += __shfl_xor_sync(0xffffffffu, ss2, 1);
    ss2 += __shfl_xor_sync(0xffffffffu, ss2, 2);
    float nrm2 = sqrtf(ss2);
    float nn  = fmaxf(nrm2, 1e-5f);
    float fac = tanhf(nn) / nn;
    float yn  = fac * nrm2;
    float pm  = fmaxf(yn, 1e-5f);
    float g2  = (pm > MAXN) ? (MAXN / pm) : 1.0f;
    float wsc = fac * g2;
    float* op = out + (size_t)n * IMG + hw;
#pragma unroll
    for (int j = 0; j < 8; j++) op[(c0 + j) << 16] = u[j] * wsc;
}

// ---------------------------------------------------------------------------
extern "C" void kernel_launch(void* const* d_in, const int* in_sizes, int n_in,
                              void* d_out, int out_size) {
    const float* x   = (const float*)d_in[0];
    const float* w1  = (const float*)d_in[1];
    const float* b1  = (const float*)d_in[2];
    const float* g1  = (const float*)d_in[3];
    const float* be1 = (const float*)d_in[4];
    const float* w2  = (const float*)d_in[5];
    const float* b2  = (const float*)d_in[6];
    const float* g2  = (const float*)d_in[7];
    const float* be2 = (const float*)d_in[8];
    float* out = (float*)d_out;

    cudaFuncSetAttribute(conv_fused_kernel<0>,
                         cudaFuncAttributeMaxDynamicSharedMemorySize, SMEM_BYTES);
    cudaFuncSetAttribute(conv_fused_kernel<1>,
                         cudaFuncAttributeMaxDynamicSharedMemorySize, SMEM_BYTES);

    dim3 cgrid(WW / 32, HH / 8, NB);   // 8 x 32 x 8 = 2048 CTAs

    pack_w_kernel<<<18, 256>>>(w1, w2);                            // 1 (+stats zero)
    noop_kernel<<<1, 32>>>();                                      // 2 (ncu align)

    conv_fused_kernel<0><<<cgrid, 256, SMEM_BYTES>>>(x, b1, nullptr, nullptr); // 3
    conv_fused_kernel<1><<<cgrid, 256, SMEM_BYTES>>>(nullptr, b2, g1, be1);    // 4

    final_kernel<<<NPIX / 64, 256>>>(g2, be2, out);                // 5
}